// round 11
// baseline (speedup 1.0000x reference)
#include <cuda_runtime.h>
#include <cuda_fp16.h>
#include <cstdint>

#define B_   64
#define P_   2304
#define SD_  1024
#define NCH  48            // p-chunks (48 p each)
#define CPP  48            // p per chunk
#define EPSQ 1e-7f

// ---------------- scratch ----------------
__device__ __half g_Wh[(size_t)P_ * SD_ * 16];     // [p][sd][k'] fp16 (75.5 MB)
__device__ __half g_uh[P_ * B_ * 16];              // [p][b][k'] fp16 (4.7 MB)
__device__ float  g_wspart[(size_t)NCH * SD_ * B_];// per-chunk ws partials (12.6 MB)
__device__ float  g_agree[2][P_ * 32];             // per-warp-parity agree partials
__device__ float  g_ws[SD_ * B_];
__device__ float  g_v [SD_ * B_];
__device__ float  g_logits[P_ * 32];
__device__ float  g_rw    [P_ * 32];

// k-permutation: groups (2q,2q+1,2q+8,2q+9) contiguously -> fragment pair = one LDG.64
__device__ __forceinline__ int kperm(int k) {
    return (k < 8) ? (((k >> 1) << 2) | (k & 1))
                   : ((((k - 8) >> 1) << 2) | 2 | (k & 1));
}

__device__ __forceinline__ void hmma16816(float* d,
                                          uint32_t a0, uint32_t a1, uint32_t a2, uint32_t a3,
                                          uint32_t b0, uint32_t b1) {
    asm volatile(
        "mma.sync.aligned.m16n8k16.row.col.f32.f16.f16.f32 "
        "{%0,%1,%2,%3}, {%4,%5,%6,%7}, {%8,%9}, {%10,%11,%12,%13};"
        : "=f"(d[0]), "=f"(d[1]), "=f"(d[2]), "=f"(d[3])
        : "r"(a0), "r"(a1), "r"(a2), "r"(a3), "r"(b0), "r"(b1),
          "f"(0.f), "f"(0.f), "f"(0.f), "f"(0.f));
}

// ---------------- init: zero logits + agree partials ----------------
__global__ void zero_init_kernel() {
    int i = blockIdx.x * blockDim.x + threadIdx.x;   // 0 .. 3*73728-1
    if (i < P_ * 32)            g_logits[i] = 0.f;
    else if (i < 2 * P_ * 32)   g_agree[0][i - P_ * 32] = 0.f;
    else                        g_agree[1][i - 2 * P_ * 32] = 0.f;
}

// ---------------- u = squash(caps) over D1 -> g_uh[p][b][k'] ----------------
__global__ void squash_u_kernel(const float* __restrict__ caps) {
    int gid = blockIdx.x * blockDim.x + threadIdx.x;   // p*64+b
    int p = gid >> 6, b = gid & 63;
    const float4* src = (const float4*)(caps + ((size_t)b * P_ + p) * 16);
    float4 a0 = src[0], a1 = src[1], a2 = src[2], a3 = src[3];
    float x[16] = {a0.x,a0.y,a0.z,a0.w, a1.x,a1.y,a1.z,a1.w,
                   a2.x,a2.y,a2.z,a2.w, a3.x,a3.y,a3.z,a3.w};
    float sq = 0.f;
    #pragma unroll
    for (int k = 0; k < 16; k++) sq += x[k] * x[k];
    float sc = (sq / (1.f + sq)) / sqrtf(sq + EPSQ);
    __half h[16];
    #pragma unroll
    for (int k = 0; k < 16; k++) h[kperm(k)] = __float2half(x[k] * sc);
    uint4* dst = (uint4*)(g_uh + (size_t)gid * 16);
    dst[0] = ((uint4*)h)[0];
    dst[1] = ((uint4*)h)[1];
}

// ---------------- W fp32 -> fp16 k-permuted ----------------
__global__ void convert_w_kernel(const float* __restrict__ W) {
    int gid = blockIdx.x * blockDim.x + threadIdx.x;   // (p,sd)
    const float4* src = (const float4*)(W + (size_t)gid * 16);
    float4 f0 = src[0], f1 = src[1], f2 = src[2], f3 = src[3];
    float x[16] = {f0.x,f0.y,f0.z,f0.w, f1.x,f1.y,f1.z,f1.w,
                   f2.x,f2.y,f2.z,f2.w, f3.x,f3.y,f3.z,f3.w};
    __half h[16];
    #pragma unroll
    for (int k = 0; k < 16; k++) h[kperm(k)] = __float2half(x[k]);
    uint4* dst = (uint4*)(g_Wh + (size_t)gid * 16);
    dst[0] = ((uint4*)h)[0];
    dst[1] = ((uint4*)h)[1];
}

// ---------------- softmax: fold agree partials into logits, then softmax ----------------
__global__ void softmax_fold_kernel() {
    int p    = blockIdx.x * 8 + (threadIdx.x >> 5);
    int lane = threadIdx.x & 31;
    int i = p * 32 + lane;
    float x = g_logits[i] + g_agree[0][i] + g_agree[1][i];
    g_logits[i] = x;
    float m = x;
    #pragma unroll
    for (int o = 16; o; o >>= 1) m = fmaxf(m, __shfl_xor_sync(0xffffffffu, m, o));
    float e = expf(x - m);
    float sum = e;
    #pragma unroll
    for (int o = 16; o; o >>= 1) sum += __shfl_xor_sync(0xffffffffu, sum, o);
    g_rw[i] = e / sum;
}

// ---------------- fused ws: partial[chunk] = sum_{p in chunk} rw*(W_p @ u_p^T) ----------------
// grid (8, NCH), 256 thr, 3 CTAs/SM. W+rw software-pipelined; u loaded in-loop (L1/L2-hot).
__global__ void __launch_bounds__(256, 3) ws_kernel() {
    int tid = threadIdx.x, wid = tid >> 5, lane = tid & 31;
    int r = lane >> 2, q = lane & 3;
    int sdb = blockIdx.x, chunk = blockIdx.y;
    int s_w = sdb * 4 + (wid >> 1);
    int sd0 = sdb * 128 + wid * 16;

    float acc[8][4];
    #pragma unroll
    for (int j = 0; j < 8; j++)
        acc[j][0] = acc[j][1] = acc[j][2] = acc[j][3] = 0.f;

    const __half* wbase = g_Wh + (size_t)(sd0 + r) * 16 + 4 * q;
    const __half* ubase = g_uh + (size_t)r * 16 + 4 * q;
    int p0 = chunk * CPP;

    // prologue: W + rw of iteration 0
    uint2 ca0, ca1; float crw;
    {
        const __half* wp = wbase + (size_t)p0 * (SD_ * 16);
        ca0 = *(const uint2*)(wp);
        ca1 = *(const uint2*)(wp + 128);
        crw = __ldg(&g_rw[p0 * 32 + s_w]);
    }

    for (int i = 0; i < CPP; i++) {
        uint2 na0, na1; float nrw;
        if (i < CPP - 1) {                    // prefetch next W pair + rw
            const __half* wp = wbase + (size_t)(p0 + i + 1) * (SD_ * 16);
            na0 = *(const uint2*)(wp);
            na1 = *(const uint2*)(wp + 128);
            nrw = __ldg(&g_rw[(p0 + i + 1) * 32 + s_w]);
        }
        const __half* up = ubase + (size_t)(p0 + i) * (64 * 16);
        uint2 cb[8];
        #pragma unroll
        for (int j = 0; j < 8; j++) cb[j] = *(const uint2*)(up + j * 128);
        #pragma unroll
        for (int j = 0; j < 8; j++) {
            float d[4];
            hmma16816(d, ca0.x, ca1.x, ca0.y, ca1.y, cb[j].x, cb[j].y);
            acc[j][0] += crw * d[0]; acc[j][1] += crw * d[1];
            acc[j][2] += crw * d[2]; acc[j][3] += crw * d[3];
        }
        ca0 = na0; ca1 = na1; crw = nrw;
    }

    float* dst = g_wspart + (size_t)chunk * (SD_ * B_);
    #pragma unroll
    for (int j = 0; j < 8; j++) {
        int b = j * 8 + 2 * q;
        *(float2*)&dst[(sd0 + r    ) * 64 + b] = make_float2(acc[j][0], acc[j][1]);
        *(float2*)&dst[(sd0 + r + 8) * 64 + b] = make_float2(acc[j][2], acc[j][3]);
    }
}

// ---------------- reduce partials -> g_ws ----------------
__global__ void reduce_ws_kernel() {
    int t = blockIdx.x * blockDim.x + threadIdx.x;    // 0..16383 (float4 units)
    const float4* p4 = (const float4*)g_wspart;
    float4 a = p4[t];
    #pragma unroll 6
    for (int c = 1; c < NCH; c++) {
        float4 v = p4[(size_t)c * 16384 + t];
        a.x += v.x; a.y += v.y; a.z += v.z; a.w += v.w;
    }
    ((float4*)g_ws)[t] = a;
}

// ---------------- v = squash(ws) over D2 ----------------
__global__ void squash_v_kernel() {
    int gid = blockIdx.x * blockDim.x + threadIdx.x;   // 0..2047
    int s = gid >> 6, b = gid & 63;
    float x[32]; float sq = 0.f;
    #pragma unroll
    for (int d = 0; d < 32; d++) { x[d] = g_ws[(s * 32 + d) * B_ + b]; sq += x[d] * x[d]; }
    float sc = (sq / (1.f + sq)) / sqrtf(sq + EPSQ);
    #pragma unroll
    for (int d = 0; d < 32; d++) g_v[(s * 32 + d) * B_ + b] = x[d] * sc;
}

// ---------------- fused agree: partial[parity][p][s] = (1/B) sum preds.v ----------------
__global__ void __launch_bounds__(256, 3) agree_kernel() {
    int tid = threadIdx.x, wid = tid >> 5, lane = tid & 31;
    int r = lane >> 2, q = lane & 3;
    int sdb = blockIdx.x, chunk = blockIdx.y;
    int s_w = sdb * 4 + (wid >> 1);
    int sd0 = sdb * 128 + wid * 16;

    // v slice in fragment layout (register-resident)
    float vf[8][4];
    #pragma unroll
    for (int j = 0; j < 8; j++) {
        int b = j * 8 + 2 * q;
        float2 v0 = *(const float2*)&g_v[(sd0 + r    ) * 64 + b];
        float2 v1 = *(const float2*)&g_v[(sd0 + r + 8) * 64 + b];
        vf[j][0] = v0.x; vf[j][1] = v0.y; vf[j][2] = v1.x; vf[j][3] = v1.y;
    }

    const __half* wbase = g_Wh + (size_t)(sd0 + r) * 16 + 4 * q;
    const __half* ubase = g_uh + (size_t)r * 16 + 4 * q;
    int p0 = chunk * CPP;
    float* out = &g_agree[wid & 1][0];

    uint2 ca0, ca1;
    {
        const __half* wp = wbase + (size_t)p0 * (SD_ * 16);
        ca0 = *(const uint2*)(wp);
        ca1 = *(const uint2*)(wp + 128);
    }

    for (int i = 0; i < CPP; i++) {
        uint2 na0, na1;
        if (i < CPP - 1) {
            const __half* wp = wbase + (size_t)(p0 + i + 1) * (SD_ * 16);
            na0 = *(const uint2*)(wp);
            na1 = *(const uint2*)(wp + 128);
        }
        const __half* up = ubase + (size_t)(p0 + i) * (64 * 16);
        uint2 cb[8];
        #pragma unroll
        for (int j = 0; j < 8; j++) cb[j] = *(const uint2*)(up + j * 128);
        float s = 0.f;
        #pragma unroll
        for (int j = 0; j < 8; j++) {
            float d[4];
            hmma16816(d, ca0.x, ca1.x, ca0.y, ca1.y, cb[j].x, cb[j].y);
            s += d[0] * vf[j][0] + d[1] * vf[j][1] + d[2] * vf[j][2] + d[3] * vf[j][3];
        }
        #pragma unroll
        for (int o = 16; o; o >>= 1) s += __shfl_xor_sync(0xffffffffu, s, o);
        if (lane == 0) out[(p0 + i) * 32 + s_w] = s * (1.f / 64.f);
        ca0 = na0; ca1 = na1;
    }
}

// ---------------- final squash -> out[b][s][d] ----------------
__global__ void final_kernel(float* __restrict__ out) {
    int gid = blockIdx.x * blockDim.x + threadIdx.x;
    int s = gid >> 6, b = gid & 63;
    float x[32]; float sq = 0.f;
    #pragma unroll
    for (int d = 0; d < 32; d++) { x[d] = g_ws[(s * 32 + d) * B_ + b]; sq += x[d] * x[d]; }
    float sc = (sq / (1.f + sq)) / sqrtf(sq + EPSQ);
    #pragma unroll
    for (int d = 0; d < 32; d++) out[(b * 32 + s) * 32 + d] = x[d] * sc;
}

// ---------------- launch ----------------
extern "C" void kernel_launch(void* const* d_in, const int* in_sizes, int n_in,
                              void* d_out, int out_size) {
    const float* caps = (const float*)d_in[0];   // [B,P,D1] fp32
    const float* W    = (const float*)d_in[1];   // [P,S,D2,D1] fp32
    float* out        = (float*)d_out;           // [B,1,S,D2] fp32

    zero_init_kernel<<<216, 1024>>>();                  // 3 * P_ * 32 = 221184
    squash_u_kernel<<<(P_ * B_) / 256, 256>>>(caps);
    convert_w_kernel<<<(P_ * SD_) / 256, 256>>>(W);

    for (int it = 0; it < 3; it++) {
        softmax_fold_kernel<<<P_ / 8, 256>>>();
        ws_kernel<<<dim3(8, NCH), 256>>>();
        reduce_ws_kernel<<<64, 256>>>();
        if (it < 2) {
            squash_v_kernel<<<8, 256>>>();
            agree_kernel<<<dim3(8, NCH), 256>>>();
        } else {
            final_kernel<<<8, 256>>>(out);
        }
    }
}

// round 13
// speedup vs baseline: 1.0272x; 1.0272x over previous
#include <cuda_runtime.h>
#include <cuda_fp16.h>
#include <cstdint>

#define B_   64
#define P_   2304
#define SD_  1024
#define NCH  36            // p-chunks (64 p each)
#define EPSQ 1e-7f

// ---------------- scratch ----------------
__device__ __half g_Wh[(size_t)P_ * SD_ * 16];     // [p][sd][k'] fp16 (75.5 MB)
__device__ __half g_uh[P_ * B_ * 16];              // [p][b][k'] fp16 (4.7 MB)
__device__ float  g_wspart[(size_t)NCH * SD_ * B_];// per-chunk ws partials (9.4 MB)
__device__ float  g_agree[2][P_ * 32];             // per-warp-parity agree partials
__device__ float  g_ws[SD_ * B_];
__device__ float  g_v [SD_ * B_];
__device__ float  g_logits[P_ * 32];
__device__ float  g_rw    [P_ * 32];

// k-permutation: groups (2q,2q+1,2q+8,2q+9) contiguously -> fragment pair = one LDG.64
__device__ __forceinline__ int kperm(int k) {
    return (k < 8) ? (((k >> 1) << 2) | (k & 1))
                   : ((((k - 8) >> 1) << 2) | 2 | (k & 1));
}

// fp16-accumulator HMMA: D/C fp16 (2 b32 regs). Layout: d[0]=(r,2q),(r,2q+1);
// d[1]=(r+8,2q),(r+8,2q+1) — same element positions as the f32 form.
__device__ __forceinline__ void hmma16816_f16(uint32_t* d,
                                              uint32_t a0, uint32_t a1, uint32_t a2, uint32_t a3,
                                              uint32_t b0, uint32_t b1) {
    asm volatile(
        "mma.sync.aligned.m16n8k16.row.col.f16.f16.f16.f16 "
        "{%0,%1}, {%2,%3,%4,%5}, {%6,%7}, {%8,%9};"
        : "=r"(d[0]), "=r"(d[1])
        : "r"(a0), "r"(a1), "r"(a2), "r"(a3), "r"(b0), "r"(b1),
          "r"(0u), "r"(0u));
}

// ---------------- init: zero logits + agree partials ----------------
__global__ void zero_init_kernel() {
    int i = blockIdx.x * blockDim.x + threadIdx.x;   // 0 .. 3*73728-1
    if (i < P_ * 32)            g_logits[i] = 0.f;
    else if (i < 2 * P_ * 32)   g_agree[0][i - P_ * 32] = 0.f;
    else                        g_agree[1][i - 2 * P_ * 32] = 0.f;
}

// ---------------- u = squash(caps) over D1 -> g_uh[p][b][k'] ----------------
__global__ void squash_u_kernel(const float* __restrict__ caps) {
    int gid = blockIdx.x * blockDim.x + threadIdx.x;   // p*64+b
    int p = gid >> 6, b = gid & 63;
    const float4* src = (const float4*)(caps + ((size_t)b * P_ + p) * 16);
    float4 a0 = src[0], a1 = src[1], a2 = src[2], a3 = src[3];
    float x[16] = {a0.x,a0.y,a0.z,a0.w, a1.x,a1.y,a1.z,a1.w,
                   a2.x,a2.y,a2.z,a2.w, a3.x,a3.y,a3.z,a3.w};
    float sq = 0.f;
    #pragma unroll
    for (int k = 0; k < 16; k++) sq += x[k] * x[k];
    float sc = (sq / (1.f + sq)) / sqrtf(sq + EPSQ);
    __half h[16];
    #pragma unroll
    for (int k = 0; k < 16; k++) h[kperm(k)] = __float2half(x[k] * sc);
    uint4* dst = (uint4*)(g_uh + (size_t)gid * 16);
    dst[0] = ((uint4*)h)[0];
    dst[1] = ((uint4*)h)[1];
}

// ---------------- W fp32 -> fp16 k-permuted ----------------
__global__ void convert_w_kernel(const float* __restrict__ W) {
    int gid = blockIdx.x * blockDim.x + threadIdx.x;   // (p,sd)
    const float4* src = (const float4*)(W + (size_t)gid * 16);
    float4 f0 = src[0], f1 = src[1], f2 = src[2], f3 = src[3];
    float x[16] = {f0.x,f0.y,f0.z,f0.w, f1.x,f1.y,f1.z,f1.w,
                   f2.x,f2.y,f2.z,f2.w, f3.x,f3.y,f3.z,f3.w};
    __half h[16];
    #pragma unroll
    for (int k = 0; k < 16; k++) h[kperm(k)] = __float2half(x[k]);
    uint4* dst = (uint4*)(g_Wh + (size_t)gid * 16);
    dst[0] = ((uint4*)h)[0];
    dst[1] = ((uint4*)h)[1];
}

// ---------------- softmax: fold agree partials into logits, then softmax ----------------
__global__ void softmax_fold_kernel() {
    int p    = blockIdx.x * 8 + (threadIdx.x >> 5);
    int lane = threadIdx.x & 31;
    int i = p * 32 + lane;
    float x = g_logits[i] + g_agree[0][i] + g_agree[1][i];
    g_logits[i] = x;
    float m = x;
    #pragma unroll
    for (int o = 16; o; o >>= 1) m = fmaxf(m, __shfl_xor_sync(0xffffffffu, m, o));
    float e = expf(x - m);
    float sum = e;
    #pragma unroll
    for (int o = 16; o; o >>= 1) sum += __shfl_xor_sync(0xffffffffu, sum, o);
    g_rw[i] = e / sum;
}

// ---------------- fused ws: partial[chunk] = sum_{p in chunk} rw*(W_p @ u_p^T) ----------------
// grid (8, NCH), 256 thr, 2 CTAs/SM. Software-pipelined (prefetch W+u of p+1).
__global__ void __launch_bounds__(256, 2) ws_kernel() {
    int tid = threadIdx.x, wid = tid >> 5, lane = tid & 31;
    int r = lane >> 2, q = lane & 3;
    int sdb = blockIdx.x, chunk = blockIdx.y;
    int s_w = sdb * 4 + (wid >> 1);
    int sd0 = sdb * 128 + wid * 16;

    float acc[8][4];
    #pragma unroll
    for (int j = 0; j < 8; j++)
        acc[j][0] = acc[j][1] = acc[j][2] = acc[j][3] = 0.f;

    const __half* wbase = g_Wh + (size_t)(sd0 + r) * 16 + 4 * q;
    const __half* ubase = g_uh + (size_t)r * 16 + 4 * q;
    int p0 = chunk * 64;

    // prologue: load iteration 0 operands
    uint2 ca0, ca1, cb[8]; float crw;
    {
        const __half* wp = wbase + (size_t)p0 * (SD_ * 16);
        ca0 = *(const uint2*)(wp);
        ca1 = *(const uint2*)(wp + 128);
        crw = __ldg(&g_rw[p0 * 32 + s_w]);
        const __half* up = ubase + (size_t)p0 * (64 * 16);
        #pragma unroll
        for (int j = 0; j < 8; j++) cb[j] = *(const uint2*)(up + j * 128);
    }

    for (int i = 0; i < 64; i++) {
        uint2 na0, na1, nb[8]; float nrw;
        if (i < 63) {                         // prefetch p+1 (independent of compute below)
            int pn = p0 + i + 1;
            const __half* wp = wbase + (size_t)pn * (SD_ * 16);
            na0 = *(const uint2*)(wp);
            na1 = *(const uint2*)(wp + 128);
            nrw = __ldg(&g_rw[pn * 32 + s_w]);
            const __half* up = ubase + (size_t)pn * (64 * 16);
            #pragma unroll
            for (int j = 0; j < 8; j++) nb[j] = *(const uint2*)(up + j * 128);
        }
        #pragma unroll
        for (int j = 0; j < 8; j++) {
            uint32_t dh[2];
            hmma16816_f16(dh, ca0.x, ca1.x, ca0.y, ca1.y, cb[j].x, cb[j].y);
            float2 lo = __half22float2(*(__half2*)&dh[0]);
            float2 hi = __half22float2(*(__half2*)&dh[1]);
            acc[j][0] += crw * lo.x; acc[j][1] += crw * lo.y;
            acc[j][2] += crw * hi.x; acc[j][3] += crw * hi.y;
        }
        ca0 = na0; ca1 = na1; crw = nrw;
        #pragma unroll
        for (int j = 0; j < 8; j++) cb[j] = nb[j];
    }

    float* dst = g_wspart + (size_t)chunk * (SD_ * B_);
    #pragma unroll
    for (int j = 0; j < 8; j++) {
        int b = j * 8 + 2 * q;
        *(float2*)&dst[(sd0 + r    ) * 64 + b] = make_float2(acc[j][0], acc[j][1]);
        *(float2*)&dst[(sd0 + r + 8) * 64 + b] = make_float2(acc[j][2], acc[j][3]);
    }
}

// ---------------- reduce partials -> g_ws ----------------
__global__ void reduce_ws_kernel() {
    int t = blockIdx.x * blockDim.x + threadIdx.x;    // 0..16383 (float4 units)
    const float4* p4 = (const float4*)g_wspart;
    float4 a = p4[t];
    #pragma unroll 5
    for (int c = 1; c < NCH; c++) {
        float4 v = p4[(size_t)c * 16384 + t];
        a.x += v.x; a.y += v.y; a.z += v.z; a.w += v.w;
    }
    ((float4*)g_ws)[t] = a;
}

// ---------------- v = squash(ws) over D2 ----------------
__global__ void squash_v_kernel() {
    int gid = blockIdx.x * blockDim.x + threadIdx.x;   // 0..2047
    int s = gid >> 6, b = gid & 63;
    float x[32]; float sq = 0.f;
    #pragma unroll
    for (int d = 0; d < 32; d++) { x[d] = g_ws[(s * 32 + d) * B_ + b]; sq += x[d] * x[d]; }
    float sc = (sq / (1.f + sq)) / sqrtf(sq + EPSQ);
    #pragma unroll
    for (int d = 0; d < 32; d++) g_v[(s * 32 + d) * B_ + b] = x[d] * sc;
}

// ---------------- fused agree: partial[parity][p][s] = (1/B) sum preds.v ----------------
__global__ void __launch_bounds__(256, 2) agree_kernel() {
    int tid = threadIdx.x, wid = tid >> 5, lane = tid & 31;
    int r = lane >> 2, q = lane & 3;
    int sdb = blockIdx.x, chunk = blockIdx.y;
    int s_w = sdb * 4 + (wid >> 1);
    int sd0 = sdb * 128 + wid * 16;

    // v slice in fragment layout (register-resident)
    float vf[8][4];
    #pragma unroll
    for (int j = 0; j < 8; j++) {
        int b = j * 8 + 2 * q;
        float2 v0 = *(const float2*)&g_v[(sd0 + r    ) * 64 + b];
        float2 v1 = *(const float2*)&g_v[(sd0 + r + 8) * 64 + b];
        vf[j][0] = v0.x; vf[j][1] = v0.y; vf[j][2] = v1.x; vf[j][3] = v1.y;
    }

    const __half* wbase = g_Wh + (size_t)(sd0 + r) * 16 + 4 * q;
    const __half* ubase = g_uh + (size_t)r * 16 + 4 * q;
    int p0 = chunk * 64;
    float* out = &g_agree[wid & 1][0];

    uint2 ca0, ca1, cb[8];
    {
        const __half* wp = wbase + (size_t)p0 * (SD_ * 16);
        ca0 = *(const uint2*)(wp);
        ca1 = *(const uint2*)(wp + 128);
        const __half* up = ubase + (size_t)p0 * (64 * 16);
        #pragma unroll
        for (int j = 0; j < 8; j++) cb[j] = *(const uint2*)(up + j * 128);
    }

    for (int i = 0; i < 64; i++) {
        uint2 na0, na1, nb[8];
        if (i < 63) {
            int pn = p0 + i + 1;
            const __half* wp = wbase + (size_t)pn * (SD_ * 16);
            na0 = *(const uint2*)(wp);
            na1 = *(const uint2*)(wp + 128);
            const __half* up = ubase + (size_t)pn * (64 * 16);
            #pragma unroll
            for (int j = 0; j < 8; j++) nb[j] = *(const uint2*)(up + j * 128);
        }
        float s = 0.f;
        #pragma unroll
        for (int j = 0; j < 8; j++) {
            uint32_t dh[2];
            hmma16816_f16(dh, ca0.x, ca1.x, ca0.y, ca1.y, cb[j].x, cb[j].y);
            float2 lo = __half22float2(*(__half2*)&dh[0]);
            float2 hi = __half22float2(*(__half2*)&dh[1]);
            s += lo.x * vf[j][0] + lo.y * vf[j][1] + hi.x * vf[j][2] + hi.y * vf[j][3];
        }
        #pragma unroll
        for (int o = 16; o; o >>= 1) s += __shfl_xor_sync(0xffffffffu, s, o);
        if (lane == 0) out[(p0 + i) * 32 + s_w] = s * (1.f / 64.f);
        ca0 = na0; ca1 = na1;
        #pragma unroll
        for (int j = 0; j < 8; j++) cb[j] = nb[j];
    }
}

// ---------------- final squash -> out[b][s][d] ----------------
__global__ void final_kernel(float* __restrict__ out) {
    int gid = blockIdx.x * blockDim.x + threadIdx.x;
    int s = gid >> 6, b = gid & 63;
    float x[32]; float sq = 0.f;
    #pragma unroll
    for (int d = 0; d < 32; d++) { x[d] = g_ws[(s * 32 + d) * B_ + b]; sq += x[d] * x[d]; }
    float sc = (sq / (1.f + sq)) / sqrtf(sq + EPSQ);
    #pragma unroll
    for (int d = 0; d < 32; d++) out[(b * 32 + s) * 32 + d] = x[d] * sc;
}

// ---------------- launch ----------------
extern "C" void kernel_launch(void* const* d_in, const int* in_sizes, int n_in,
                              void* d_out, int out_size) {
    const float* caps = (const float*)d_in[0];   // [B,P,D1] fp32
    const float* W    = (const float*)d_in[1];   // [P,S,D2,D1] fp32
    float* out        = (float*)d_out;           // [B,1,S,D2] fp32

    zero_init_kernel<<<216, 1024>>>();                  // 3 * P_ * 32 = 221184
    squash_u_kernel<<<(P_ * B_) / 256, 256>>>(caps);
    convert_w_kernel<<<(P_ * SD_) / 256, 256>>>(W);

    for (int it = 0; it < 3; it++) {
        softmax_fold_kernel<<<P_ / 8, 256>>>();
        ws_kernel<<<dim3(8, NCH), 256>>>();
        reduce_ws_kernel<<<64, 256>>>();
        if (it < 2) {
            squash_v_kernel<<<8, 256>>>();
            agree_kernel<<<dim3(8, NCH), 256>>>();
        } else {
            final_kernel<<<8, 256>>>(out);
        }
    }
}

// round 15
// speedup vs baseline: 1.1365x; 1.1063x over previous
#include <cuda_runtime.h>
#include <cuda_fp16.h>
#include <cstdint>

#define B_   64
#define P_   2304
#define SD_  1024
#define NCH  72            // p-chunks (32 p each)
#define CPP  32
#define EPSQ 1e-7f

// ---------------- scratch ----------------
__device__ __half g_Wh[(size_t)P_ * SD_ * 16];     // [p][sd][k'] fp16 (75.5 MB)
__device__ __half g_uh[P_ * B_ * 16];              // [p][b][k'] fp16 (4.7 MB)
__device__ float  g_wspart[(size_t)NCH * SD_ * B_];// per-chunk ws partials (18.9 MB)
__device__ float  g_ws[SD_ * B_];
__device__ float  g_v [SD_ * B_];
__device__ float  g_logits[P_ * 32];
__device__ float  g_rw    [P_ * 32];

// k-permutation: groups (2q,2q+1,2q+8,2q+9) contiguously -> fragment pair = one LDG.64
__device__ __forceinline__ int kperm(int k) {
    return (k < 8) ? (((k >> 1) << 2) | (k & 1))
                   : ((((k - 8) >> 1) << 2) | 2 | (k & 1));
}

__device__ __forceinline__ void hmma16816(float* d,
                                          uint32_t a0, uint32_t a1, uint32_t a2, uint32_t a3,
                                          uint32_t b0, uint32_t b1) {
    asm volatile(
        "mma.sync.aligned.m16n8k16.row.col.f32.f16.f16.f32 "
        "{%0,%1,%2,%3}, {%4,%5,%6,%7}, {%8,%9}, {%10,%11,%12,%13};"
        : "=f"(d[0]), "=f"(d[1]), "=f"(d[2]), "=f"(d[3])
        : "r"(a0), "r"(a1), "r"(a2), "r"(a3), "r"(b0), "r"(b1),
          "f"(0.f), "f"(0.f), "f"(0.f), "f"(0.f));
}

// ---------------- init ----------------
__global__ void zero_logits_kernel() {
    int i = blockIdx.x * blockDim.x + threadIdx.x;
    if (i < P_ * 32) g_logits[i] = 0.f;
}

// ---------------- u = squash(caps) over D1 -> g_uh[p][b][k'] ----------------
__global__ void squash_u_kernel(const float* __restrict__ caps) {
    int gid = blockIdx.x * blockDim.x + threadIdx.x;   // p*64+b
    int p = gid >> 6, b = gid & 63;
    const float4* src = (const float4*)(caps + ((size_t)b * P_ + p) * 16);
    float4 a0 = src[0], a1 = src[1], a2 = src[2], a3 = src[3];
    float x[16] = {a0.x,a0.y,a0.z,a0.w, a1.x,a1.y,a1.z,a1.w,
                   a2.x,a2.y,a2.z,a2.w, a3.x,a3.y,a3.z,a3.w};
    float sq = 0.f;
    #pragma unroll
    for (int k = 0; k < 16; k++) sq += x[k] * x[k];
    float sc = (sq / (1.f + sq)) / sqrtf(sq + EPSQ);
    __half h[16];
    #pragma unroll
    for (int k = 0; k < 16; k++) h[kperm(k)] = __float2half(x[k] * sc);
    uint4* dst = (uint4*)(g_uh + (size_t)gid * 16);
    dst[0] = ((uint4*)h)[0];
    dst[1] = ((uint4*)h)[1];
}

// ---------------- W fp32 -> fp16 k-permuted ----------------
__global__ void convert_w_kernel(const float* __restrict__ W) {
    int gid = blockIdx.x * blockDim.x + threadIdx.x;   // (p,sd)
    const float4* src = (const float4*)(W + (size_t)gid * 16);
    float4 f0 = src[0], f1 = src[1], f2 = src[2], f3 = src[3];
    float x[16] = {f0.x,f0.y,f0.z,f0.w, f1.x,f1.y,f1.z,f1.w,
                   f2.x,f2.y,f2.z,f2.w, f3.x,f3.y,f3.z,f3.w};
    __half h[16];
    #pragma unroll
    for (int k = 0; k < 16; k++) h[kperm(k)] = __float2half(x[k]);
    uint4* dst = (uint4*)(g_Wh + (size_t)gid * 16);
    dst[0] = ((uint4*)h)[0];
    dst[1] = ((uint4*)h)[1];
}

// ---------------- softmax over S ----------------
__global__ void softmax_kernel() {
    int p    = blockIdx.x * 8 + (threadIdx.x >> 5);
    int lane = threadIdx.x & 31;
    float x = g_logits[p * 32 + lane];
    float m = x;
    #pragma unroll
    for (int o = 16; o; o >>= 1) m = fmaxf(m, __shfl_xor_sync(0xffffffffu, m, o));
    float e = expf(x - m);
    float sum = e;
    #pragma unroll
    for (int o = 16; o; o >>= 1) sum += __shfl_xor_sync(0xffffffffu, sum, o);
    g_rw[p * 32 + lane] = e / sum;
}

// ---------------- fused ws: 32 sd rows per warp (2 m-tiles), one s per warp ----------------
// grid (4, NCH), 256 thr, 2 CTAs/SM.
__global__ void __launch_bounds__(256, 2) ws_kernel() {
    int tid = threadIdx.x, wid = tid >> 5, lane = tid & 31;
    int r = lane >> 2, q = lane & 3;
    int sdb = blockIdx.x, chunk = blockIdx.y;
    int s_w = sdb * 8 + wid;                 // warp's s
    int sd0 = sdb * 256 + wid * 32;

    float acc[2][8][4];
    #pragma unroll
    for (int m = 0; m < 2; m++)
        #pragma unroll
        for (int j = 0; j < 8; j++)
            acc[m][j][0] = acc[m][j][1] = acc[m][j][2] = acc[m][j][3] = 0.f;

    const __half* wbase = g_Wh + (size_t)(sd0 + r) * 16 + 4 * q;
    const __half* ubase = g_uh + (size_t)r * 16 + 4 * q;
    int p0 = chunk * CPP;

    // prologue: W (4 pairs) + rw of iteration 0
    uint2 ca[4]; float crw;
    {
        const __half* wp = wbase + (size_t)p0 * (SD_ * 16);
        ca[0] = *(const uint2*)(wp);        // tile0 row r
        ca[1] = *(const uint2*)(wp + 128);  // tile0 row r+8
        ca[2] = *(const uint2*)(wp + 256);  // tile1 row r+16
        ca[3] = *(const uint2*)(wp + 384);  // tile1 row r+24
        crw = __ldg(&g_rw[p0 * 32 + s_w]);
    }

    for (int i = 0; i < CPP; i++) {
        uint2 na[4]; float nrw;
        if (i < CPP - 1) {
            const __half* wp = wbase + (size_t)(p0 + i + 1) * (SD_ * 16);
            na[0] = *(const uint2*)(wp);
            na[1] = *(const uint2*)(wp + 128);
            na[2] = *(const uint2*)(wp + 256);
            na[3] = *(const uint2*)(wp + 384);
            nrw = __ldg(&g_rw[(p0 + i + 1) * 32 + s_w]);
        }
        const __half* up = ubase + (size_t)(p0 + i) * (64 * 16);
        uint2 cb[8];
        #pragma unroll
        for (int j = 0; j < 8; j++) cb[j] = *(const uint2*)(up + j * 128);
        #pragma unroll
        for (int j = 0; j < 8; j++) {
            float d[4];
            hmma16816(d, ca[0].x, ca[1].x, ca[0].y, ca[1].y, cb[j].x, cb[j].y);
            acc[0][j][0] += crw * d[0]; acc[0][j][1] += crw * d[1];
            acc[0][j][2] += crw * d[2]; acc[0][j][3] += crw * d[3];
            hmma16816(d, ca[2].x, ca[3].x, ca[2].y, ca[3].y, cb[j].x, cb[j].y);
            acc[1][j][0] += crw * d[0]; acc[1][j][1] += crw * d[1];
            acc[1][j][2] += crw * d[2]; acc[1][j][3] += crw * d[3];
        }
        #pragma unroll
        for (int t = 0; t < 4; t++) ca[t] = na[t];
        crw = nrw;
    }

    float* dst = g_wspart + (size_t)chunk * (SD_ * B_);
    #pragma unroll
    for (int m = 0; m < 2; m++)
        #pragma unroll
        for (int j = 0; j < 8; j++) {
            int b = j * 8 + 2 * q;
            int row = sd0 + m * 16 + r;
            *(float2*)&dst[(row    ) * 64 + b] = make_float2(acc[m][j][0], acc[m][j][1]);
            *(float2*)&dst[(row + 8) * 64 + b] = make_float2(acc[m][j][2], acc[m][j][3]);
        }
}

// ---------------- reduce partials -> g_ws ----------------
__global__ void reduce_ws_kernel() {
    int t = blockIdx.x * blockDim.x + threadIdx.x;    // 0..16383 (float4 units)
    const float4* p4 = (const float4*)g_wspart;
    float4 a = p4[t];
    #pragma unroll 8
    for (int c = 1; c < NCH; c++) {
        float4 v = p4[(size_t)c * 16384 + t];
        a.x += v.x; a.y += v.y; a.z += v.z; a.w += v.w;
    }
    ((float4*)g_ws)[t] = a;
}

// ---------------- v = squash(ws) over D2 ----------------
__global__ void squash_v_kernel() {
    int gid = blockIdx.x * blockDim.x + threadIdx.x;   // 0..2047
    int s = gid >> 6, b = gid & 63;
    float x[32]; float sq = 0.f;
    #pragma unroll
    for (int d = 0; d < 32; d++) { x[d] = g_ws[(s * 32 + d) * B_ + b]; sq += x[d] * x[d]; }
    float sc = (sq / (1.f + sq)) / sqrtf(sq + EPSQ);
    #pragma unroll
    for (int d = 0; d < 32; d++) g_v[(s * 32 + d) * B_ + b] = x[d] * sc;
}

// ---------------- fused agree: one s per warp, single writer -> logits += directly ----------------
__global__ void __launch_bounds__(256, 2) agree_kernel() {
    int tid = threadIdx.x, wid = tid >> 5, lane = tid & 31;
    int r = lane >> 2, q = lane & 3;
    int sdb = blockIdx.x, chunk = blockIdx.y;
    int s_w = sdb * 8 + wid;
    int sd0 = sdb * 256 + wid * 32;

    // v slice (32 rows x 64 cols) in fragment layout
    float vf[2][8][4];
    #pragma unroll
    for (int m = 0; m < 2; m++)
        #pragma unroll
        for (int j = 0; j < 8; j++) {
            int b = j * 8 + 2 * q;
            int row = sd0 + m * 16 + r;
            float2 v0 = *(const float2*)&g_v[(row    ) * 64 + b];
            float2 v1 = *(const float2*)&g_v[(row + 8) * 64 + b];
            vf[m][j][0] = v0.x; vf[m][j][1] = v0.y; vf[m][j][2] = v1.x; vf[m][j][3] = v1.y;
        }

    const __half* wbase = g_Wh + (size_t)(sd0 + r) * 16 + 4 * q;
    const __half* ubase = g_uh + (size_t)r * 16 + 4 * q;
    int p0 = chunk * CPP;

    uint2 ca[4];
    {
        const __half* wp = wbase + (size_t)p0 * (SD_ * 16);
        ca[0] = *(const uint2*)(wp);
        ca[1] = *(const uint2*)(wp + 128);
        ca[2] = *(const uint2*)(wp + 256);
        ca[3] = *(const uint2*)(wp + 384);
    }

    for (int i = 0; i < CPP; i++) {
        uint2 na[4];
        if (i < CPP - 1) {
            const __half* wp = wbase + (size_t)(p0 + i + 1) * (SD_ * 16);
            na[0] = *(const uint2*)(wp);
            na[1] = *(const uint2*)(wp + 128);
            na[2] = *(const uint2*)(wp + 256);
            na[3] = *(const uint2*)(wp + 384);
        }
        const __half* up = ubase + (size_t)(p0 + i) * (64 * 16);
        uint2 cb[8];
        #pragma unroll
        for (int j = 0; j < 8; j++) cb[j] = *(const uint2*)(up + j * 128);
        float s = 0.f;
        #pragma unroll
        for (int j = 0; j < 8; j++) {
            float d[4];
            hmma16816(d, ca[0].x, ca[1].x, ca[0].y, ca[1].y, cb[j].x, cb[j].y);
            s += d[0] * vf[0][j][0] + d[1] * vf[0][j][1] + d[2] * vf[0][j][2] + d[3] * vf[0][j][3];
            hmma16816(d, ca[2].x, ca[3].x, ca[2].y, ca[3].y, cb[j].x, cb[j].y);
            s += d[0] * vf[1][j][0] + d[1] * vf[1][j][1] + d[2] * vf[1][j][2] + d[3] * vf[1][j][3];
        }
        #pragma unroll
        for (int o = 16; o; o >>= 1) s += __shfl_xor_sync(0xffffffffu, s, o);
        if (lane == 0) {
            int idx = (p0 + i) * 32 + s_w;          // single writer per (p,s)
            g_logits[idx] += s * (1.f / 64.f);
        }
        #pragma unroll
        for (int t = 0; t < 4; t++) ca[t] = na[t];
    }
}

// ---------------- final squash -> out[b][s][d] ----------------
__global__ void final_kernel(float* __restrict__ out) {
    int gid = blockIdx.x * blockDim.x + threadIdx.x;
    int s = gid >> 6, b = gid & 63;
    float x[32]; float sq = 0.f;
    #pragma unroll
    for (int d = 0; d < 32; d++) { x[d] = g_ws[(s * 32 + d) * B_ + b]; sq += x[d] * x[d]; }
    float sc = (sq / (1.f + sq)) / sqrtf(sq + EPSQ);
    #pragma unroll
    for (int d = 0; d < 32; d++) out[(b * 32 + s) * 32 + d] = x[d] * sc;
}

// ---------------- launch ----------------
extern "C" void kernel_launch(void* const* d_in, const int* in_sizes, int n_in,
                              void* d_out, int out_size) {
    const float* caps = (const float*)d_in[0];   // [B,P,D1] fp32
    const float* W    = (const float*)d_in[1];   // [P,S,D2,D1] fp32
    float* out        = (float*)d_out;           // [B,1,S,D2] fp32

    zero_logits_kernel<<<P_ * 32 / 256, 256>>>();
    squash_u_kernel<<<(P_ * B_) / 256, 256>>>(caps);
    convert_w_kernel<<<(P_ * SD_) / 256, 256>>>(W);

    for (int it = 0; it < 3; it++) {
        softmax_kernel<<<P_ / 8, 256>>>();
        ws_kernel<<<dim3(4, NCH), 256>>>();
        reduce_ws_kernel<<<64, 256>>>();
        if (it < 2) {
            squash_v_kernel<<<8, 256>>>();
            agree_kernel<<<dim3(4, NCH), 256>>>();
        } else {
            final_kernel<<<8, 256>>>(out);
        }
    }
}